// round 8
// baseline (speedup 1.0000x reference)
#include <cuda_runtime.h>
#include <cuda_fp16.h>
#include <cstdint>

#define NN 100000
#define EE 1600000
#define NEG_SLOPE 0.2f
#define LN_EPS 1e-5f
#define NCHUNK 98  // ceil(NN/1024)

// ---------------- scratch (device globals; no allocation allowed) ----------------
__device__ __half  g_feat16[(size_t)NN * 128]; // h @ W in fp16 (25.6 MB, L2-resident)
__device__ float   g_el[NN * 2];
__device__ float   g_er[NN * 2];
__device__ float   g_wl[256];                  // [wl_head0(128), wl_head1(128)] = W·attn_l
__device__ float   g_wr[256];                  // [wr_head0(128), wr_head1(128)] = W·attn_r
__device__ int     g_deg[NN];
__device__ int     g_rowptr[NN + 1];
__device__ int     g_cursor[NN];
__device__ int     g_chunk_sum[128];
__device__ int     g_chunk_excl[128];
__device__ uint2   g_csr[EE];                  // {src, half2{exp_e0, exp_e1}} -- 8B/edge

// ---------------- 0: zero degree counters ----------------
__global__ void zero_deg_kernel() {
    int i = blockIdx.x * blockDim.x + threadIdx.x;
    if (i < NN) g_deg[i] = 0;
}

// ---------------- 0b: wl/wr = W @ attn vectors (tiny, 1 block) ----------------
// wl_h[k] = sum_f W[k, h*64+f] * attn_l[h*64+f]
__global__ void wlr_kernel(const float* __restrict__ W, const float* __restrict__ attn_l,
                           const float* __restrict__ attn_r) {
    __shared__ float al[128], ar[128];
    int t = threadIdx.x;  // 128 threads, one k each
    al[t] = attn_l[t];
    ar[t] = attn_r[t];
    __syncthreads();
    const float* Wr = W + (size_t)t * 128;
    float l0 = 0.f, l1 = 0.f, r0 = 0.f, r1 = 0.f;
#pragma unroll 16
    for (int f = 0; f < 64; f++) {
        float w0 = Wr[f], w1 = Wr[64 + f];
        l0 += w0 * al[f];      r0 += w0 * ar[f];
        l1 += w1 * al[64 + f]; r1 += w1 * ar[64 + f];
    }
    g_wl[t] = l0; g_wl[128 + t] = l1;
    g_wr[t] = r0; g_wr[128 + t] = r1;
}

// ---------------- 0c: el/er GEMV from h directly (one warp per row) ----------------
__global__ void elr_kernel(const float* __restrict__ h) {
    int row = (blockIdx.x * blockDim.x + threadIdx.x) >> 5;
    int lane = threadIdx.x & 31;
    if (row >= NN) return;
    int c = lane * 4;
    float4 v   = *(const float4*)(h + (size_t)row * 128 + c);
    float4 wl0 = *(const float4*)(g_wl + c);
    float4 wl1 = *(const float4*)(g_wl + 128 + c);
    float4 wr0 = *(const float4*)(g_wr + c);
    float4 wr1 = *(const float4*)(g_wr + 128 + c);
    float el0 = v.x * wl0.x + v.y * wl0.y + v.z * wl0.z + v.w * wl0.w;
    float el1 = v.x * wl1.x + v.y * wl1.y + v.z * wl1.z + v.w * wl1.w;
    float er0 = v.x * wr0.x + v.y * wr0.y + v.z * wr0.z + v.w * wr0.w;
    float er1 = v.x * wr1.x + v.y * wr1.y + v.z * wr1.z + v.w * wr1.w;
#pragma unroll
    for (int off = 16; off; off >>= 1) {
        el0 += __shfl_xor_sync(0xffffffffu, el0, off);
        el1 += __shfl_xor_sync(0xffffffffu, el1, off);
        er0 += __shfl_xor_sync(0xffffffffu, er0, off);
        er1 += __shfl_xor_sync(0xffffffffu, er1, off);
    }
    if (lane == 0) {
        g_el[2 * row] = el0; g_el[2 * row + 1] = el1;
        g_er[2 * row] = er0; g_er[2 * row + 1] = er1;
    }
}

// ---------------- 1: feat = h@W (FFMA; feat-only epilogue) ----------------
#define KT 32
#define HS 68   // padded row stride (floats) for transposed h tile
__global__ void gemm_kernel(const float* __restrict__ h, const float* __restrict__ W) {
    __shared__ float Wsh[KT * 128];   // 16 KB
    __shared__ float hsh[KT * HS];    // 8.7 KB
    int tid = threadIdx.x;
    int lane = tid & 31, wid = tid >> 5;
    int row0 = blockIdx.x * 64;

    float4 acc[8];
#pragma unroll
    for (int r = 0; r < 8; r++) acc[r] = make_float4(0.f, 0.f, 0.f, 0.f);

    for (int t = 0; t < 4; t++) {
        __syncthreads();
        {
            const float4* Wg = (const float4*)(W + t * KT * 128);
            float4* Ws = (float4*)Wsh;
            for (int j = tid; j < KT * 32; j += 256) Ws[j] = Wg[j];
        }
        for (int j = tid; j < 64 * (KT / 4); j += 256) {
            int r = j >> 3, c4 = j & 7;
            int row = row0 + r;
            float4 v = make_float4(0.f, 0.f, 0.f, 0.f);
            if (row < NN) v = *(const float4*)(h + (size_t)row * 128 + t * KT + c4 * 4);
            hsh[(c4 * 4 + 0) * HS + r] = v.x;
            hsh[(c4 * 4 + 1) * HS + r] = v.y;
            hsh[(c4 * 4 + 2) * HS + r] = v.z;
            hsh[(c4 * 4 + 3) * HS + r] = v.w;
        }
        __syncthreads();
#pragma unroll 4
        for (int kk = 0; kk < KT; kk++) {
            float4 b  = ((const float4*)(Wsh + kk * 128))[lane];
            float4 alo = *(const float4*)(hsh + kk * HS + wid * 8);
            float4 ahi = *(const float4*)(hsh + kk * HS + wid * 8 + 4);
            acc[0].x += alo.x * b.x; acc[0].y += alo.x * b.y; acc[0].z += alo.x * b.z; acc[0].w += alo.x * b.w;
            acc[1].x += alo.y * b.x; acc[1].y += alo.y * b.y; acc[1].z += alo.y * b.z; acc[1].w += alo.y * b.w;
            acc[2].x += alo.z * b.x; acc[2].y += alo.z * b.y; acc[2].z += alo.z * b.z; acc[2].w += alo.z * b.w;
            acc[3].x += alo.w * b.x; acc[3].y += alo.w * b.y; acc[3].z += alo.w * b.z; acc[3].w += alo.w * b.w;
            acc[4].x += ahi.x * b.x; acc[4].y += ahi.x * b.y; acc[4].z += ahi.x * b.z; acc[4].w += ahi.x * b.w;
            acc[5].x += ahi.y * b.x; acc[5].y += ahi.y * b.y; acc[5].z += ahi.y * b.z; acc[5].w += ahi.y * b.w;
            acc[6].x += ahi.z * b.x; acc[6].y += ahi.z * b.y; acc[6].z += ahi.z * b.z; acc[6].w += ahi.z * b.w;
            acc[7].x += ahi.w * b.x; acc[7].y += ahi.w * b.y; acc[7].z += ahi.w * b.z; acc[7].w += ahi.w * b.w;
        }
    }

#pragma unroll
    for (int r = 0; r < 8; r++) {
        int row = row0 + wid * 8 + r;
        if (row >= NN) continue;
        __half2 p0 = __floats2half2_rn(acc[r].x, acc[r].y);
        __half2 p1 = __floats2half2_rn(acc[r].z, acc[r].w);
        uint2 hv;
        hv.x = *(uint32_t*)&p0;
        hv.y = *(uint32_t*)&p1;
        *(uint2*)(g_feat16 + (size_t)row * 128 + lane * 4) = hv;
    }
}

// ---------------- 2: degree histogram ----------------
__global__ void hist_kernel(const int* __restrict__ dst) {
    int e = blockIdx.x * blockDim.x + threadIdx.x;
    if (e < EE) atomicAdd(&g_deg[dst[e]], 1);
}

// ---------------- 3a: per-chunk sums (chunk = 1024) ----------------
__global__ void chunk_sum_kernel() {
    int b = blockIdx.x, t = threadIdx.x;
    int base = b * 1024;
    int s = 0;
    for (int j = t; j < 1024; j += 256) {
        int i = base + j;
        s += (i < NN) ? g_deg[i] : 0;
    }
    __shared__ int sh[8];
#pragma unroll
    for (int off = 16; off; off >>= 1) s += __shfl_xor_sync(0xffffffffu, s, off);
    if ((t & 31) == 0) sh[t >> 5] = s;
    __syncthreads();
    if (t < 32) {
        int v = (t < 8) ? sh[t] : 0;
#pragma unroll
        for (int off = 4; off; off >>= 1) v += __shfl_xor_sync(0xffffffffu, v, off);
        if (t == 0) g_chunk_sum[b] = v;
    }
}

// ---------------- 3b: scan chunk sums (1 block) ----------------
__global__ void scan_chunks_kernel() {
    __shared__ int sh[128];
    int t = threadIdx.x;
    int v = (t < NCHUNK) ? g_chunk_sum[t] : 0;
    sh[t] = v;
    __syncthreads();
    for (int off = 1; off < 128; off <<= 1) {
        int a = (t >= off) ? sh[t - off] : 0;
        __syncthreads();
        sh[t] += a;
        __syncthreads();
    }
    if (t < NCHUNK) g_chunk_excl[t] = sh[t] - v;
}

// ---------------- 3c: finalize row_ptr / cursor ----------------
__global__ void scan_final_kernel() {
    int i = blockIdx.x * 1024 + threadIdx.x;
    int lane = threadIdx.x & 31, wid = threadIdx.x >> 5;
    int v = (i < NN) ? g_deg[i] : 0;
    int x = v;
#pragma unroll
    for (int off = 1; off < 32; off <<= 1) {
        int y = __shfl_up_sync(0xffffffffu, x, off);
        if (lane >= off) x += y;
    }
    __shared__ int sh[32];
    if (lane == 31) sh[wid] = x;
    __syncthreads();
    if (wid == 0) {
        int y = sh[lane];
#pragma unroll
        for (int off = 1; off < 32; off <<= 1) {
            int z = __shfl_up_sync(0xffffffffu, y, off);
            if (lane >= off) y += z;
        }
        sh[lane] = y;
    }
    __syncthreads();
    int incl = x + (wid ? sh[wid - 1] : 0);
    int base = g_chunk_excl[blockIdx.x];
    if (i < NN) {
        int excl = base + incl - v;
        g_rowptr[i] = excl;
        g_cursor[i] = excl;
    }
    if (i == NN - 1) g_rowptr[NN] = base + incl;
}

// ---------------- 4: scatter edges into CSR order with exp(logit), 8B entries ----------------
__global__ void scatter_kernel(const int* __restrict__ src, const int* __restrict__ dst) {
    int e = blockIdx.x * blockDim.x + threadIdx.x;
    if (e >= EE) return;
    int s = src[e], d = dst[e];
    int p = atomicAdd(&g_cursor[d], 1);
    float e0 = g_el[2 * s]     + g_er[2 * d];
    float e1 = g_el[2 * s + 1] + g_er[2 * d + 1];
    e0 = (e0 > 0.f) ? e0 : NEG_SLOPE * e0;
    e1 = (e1 > 0.f) ? e1 : NEG_SLOPE * e1;
    __half2 w = __floats2half2_rn(__expf(e0), __expf(e1));
    g_csr[p] = make_uint2((uint32_t)s, *(uint32_t*)&w);
}

// ---------------- 5: per-node weighted aggregate + fused LayerNorm ----------------
__global__ void agg_ln_kernel(const float* __restrict__ bias, const float* __restrict__ gamma,
                              const float* __restrict__ beta, float* __restrict__ out) {
    int gwarp = (blockIdx.x * blockDim.x + threadIdx.x) >> 5;
    int lane = threadIdx.x & 31;
    if (gwarp >= NN) return;
    int beg = g_rowptr[gwarp], end = g_rowptr[gwarp + 1];
    bool h1 = (lane >= 16);

    float4 acc = make_float4(0.f, 0.f, 0.f, 0.f);
    float wsum = 0.f;
    int i = beg;
    for (; i + 2 <= end; i += 2) {
        uint2 c0 = g_csr[i], c1 = g_csr[i + 1];
        uint2 u0 = ((const uint2*)(g_feat16 + (size_t)c0.x * 128))[lane];
        uint2 u1 = ((const uint2*)(g_feat16 + (size_t)c1.x * 128))[lane];
        __half2 wh0 = *(__half2*)&c0.y, wh1 = *(__half2*)&c1.y;
        float w0 = h1 ? __high2float(wh0) : __low2float(wh0);
        float w1 = h1 ? __high2float(wh1) : __low2float(wh1);
        float2 v0a = __half22float2(*(__half2*)&u0.x);
        float2 v0b = __half22float2(*(__half2*)&u0.y);
        float2 v1a = __half22float2(*(__half2*)&u1.x);
        float2 v1b = __half22float2(*(__half2*)&u1.y);
        wsum += w0 + w1;
        acc.x += w0 * v0a.x + w1 * v1a.x;
        acc.y += w0 * v0a.y + w1 * v1a.y;
        acc.z += w0 * v0b.x + w1 * v1b.x;
        acc.w += w0 * v0b.y + w1 * v1b.y;
    }
    if (i < end) {
        uint2 c0 = g_csr[i];
        uint2 u0 = ((const uint2*)(g_feat16 + (size_t)c0.x * 128))[lane];
        __half2 wh0 = *(__half2*)&c0.y;
        float w0 = h1 ? __high2float(wh0) : __low2float(wh0);
        float2 v0a = __half22float2(*(__half2*)&u0.x);
        float2 v0b = __half22float2(*(__half2*)&u0.y);
        wsum += w0;
        acc.x += w0 * v0a.x; acc.y += w0 * v0a.y;
        acc.z += w0 * v0b.x; acc.w += w0 * v0b.y;
    }
    float inv = (end > beg) ? 1.0f / wsum : 0.f;

    float4 b4 = ((const float4*)bias)[lane];
    float4 x;
    x.x = acc.x * inv + b4.x; x.y = acc.y * inv + b4.y;
    x.z = acc.z * inv + b4.z; x.w = acc.w * inv + b4.w;

    float s = x.x + x.y + x.z + x.w;
#pragma unroll
    for (int off = 16; off; off >>= 1) s += __shfl_xor_sync(0xffffffffu, s, off);
    float mu = s * (1.f / 128.f);
    float dx0 = x.x - mu, dx1 = x.y - mu, dx2 = x.z - mu, dx3 = x.w - mu;
    float ss = dx0 * dx0 + dx1 * dx1 + dx2 * dx2 + dx3 * dx3;
#pragma unroll
    for (int off = 16; off; off >>= 1) ss += __shfl_xor_sync(0xffffffffu, ss, off);
    float istd = rsqrtf(ss * (1.f / 128.f) + LN_EPS);

    float4 g4 = ((const float4*)gamma)[lane];
    float4 be4 = ((const float4*)beta)[lane];
    float4 y;
    y.x = g4.x * dx0 * istd + be4.x;
    y.y = g4.y * dx1 * istd + be4.y;
    y.z = g4.z * dx2 * istd + be4.z;
    y.w = g4.w * dx3 * istd + be4.w;
    ((float4*)(out + (size_t)gwarp * 128))[lane] = y;
}

// ---------------- launch: full CSR+logit chain on side stream, overlapped with gemm ----------------
extern "C" void kernel_launch(void* const* d_in, const int* in_sizes, int n_in,
                              void* d_out, int out_size) {
    const float* h      = (const float*)d_in[0];
    const int*   src    = (const int*)d_in[1];
    const int*   dst    = (const int*)d_in[2];
    const float* W      = (const float*)d_in[3];
    const float* attn_l = (const float*)d_in[4];
    const float* attn_r = (const float*)d_in[5];
    const float* bias   = (const float*)d_in[6];
    const float* gamma  = (const float*)d_in[7];
    const float* beta   = (const float*)d_in[8];
    float* out = (float*)d_out;

    static cudaStream_t s1 = nullptr;
    static cudaEvent_t evRoot = nullptr, evSide = nullptr;
    if (!s1) {
        cudaStreamCreateWithFlags(&s1, cudaStreamNonBlocking);
        cudaEventCreateWithFlags(&evRoot, cudaEventDisableTiming);
        cudaEventCreateWithFlags(&evSide, cudaEventDisableTiming);
    }

    // fork: entire edge-side chain on s1 (independent of the big gemm)
    cudaEventRecord(evRoot, 0);
    cudaStreamWaitEvent(s1, evRoot, 0);

    zero_deg_kernel<<<(NN + 255) / 256, 256, 0, s1>>>();
    hist_kernel<<<(EE + 255) / 256, 256, 0, s1>>>(dst);
    wlr_kernel<<<1, 128, 0, s1>>>(W, attn_l, attn_r);
    elr_kernel<<<(NN * 32 + 255) / 256, 256, 0, s1>>>(h);
    chunk_sum_kernel<<<NCHUNK, 256, 0, s1>>>();
    scan_chunks_kernel<<<1, 128, 0, s1>>>();
    scan_final_kernel<<<NCHUNK, 1024, 0, s1>>>();
    scatter_kernel<<<(EE + 255) / 256, 256, 0, s1>>>(src, dst);
    cudaEventRecord(evSide, s1);

    // main stream: the big gemm (feat only)
    gemm_kernel<<<(NN + 63) / 64, 256>>>(h, W);

    // join: agg needs feat (main) + csr (side)
    cudaStreamWaitEvent(0, evSide, 0);
    agg_ln_kernel<<<(NN * 32 + 255) / 256, 256>>>(bias, gamma, beta, out);
}

// round 9
// speedup vs baseline: 1.1489x; 1.1489x over previous
#include <cuda_runtime.h>
#include <cuda_fp16.h>
#include <cuda_bf16.h>
#include <cstdint>

#define NN 100000
#define EE 1600000
#define NEG_SLOPE 0.2f
#define LN_EPS 1e-5f
#define NCHUNK 98  // ceil(NN/1024)

// ---------------- scratch (device globals; no allocation allowed) ----------------
__device__ __half         g_feat16[(size_t)NN * 128]; // h @ W in fp16 (25.6 MB)
__device__ __nv_bfloat16  g_hHi[(size_t)NN * 128];    // bf16 hi split of h (25.6 MB)
__device__ __nv_bfloat16  g_hLo[(size_t)NN * 128];    // bf16 lo split of h (25.6 MB)
__device__ __nv_bfloat16  g_WtHi[128 * 128];          // Wt[n][k] hi
__device__ __nv_bfloat16  g_WtLo[128 * 128];          // Wt[n][k] lo
__device__ float   g_el[NN * 2];
__device__ float   g_er[NN * 2];
__device__ int     g_deg[NN];
__device__ int     g_rowptr[NN + 1];
__device__ int     g_cursor[NN];
__device__ int     g_chunk_sum[128];
__device__ int     g_chunk_excl[128];
__device__ uint2   g_csr[EE];                  // {src, half2{exp_e0, exp_e1}} -- 8B/edge

__device__ __forceinline__ uint32_t pack_bf16(float a, float b) {
    __nv_bfloat162 t = __floats2bfloat162_rn(a, b);
    return *reinterpret_cast<uint32_t*>(&t);
}

// ---------------- 0: zero degree counters ----------------
__global__ void zero_deg_kernel() {
    int i = blockIdx.x * blockDim.x + threadIdx.x;
    if (i < NN) g_deg[i] = 0;
}

// ---------------- 0b: split h into bf16 hi/lo (streaming) ----------------
__global__ void conv_h_kernel(const float* __restrict__ h) {
    size_t j = (size_t)blockIdx.x * blockDim.x + threadIdx.x;  // one float4
    if (j >= (size_t)NN * 32) return;
    float4 v = ((const float4*)h)[j];
    __nv_bfloat16 h0 = __float2bfloat16(v.x), h1 = __float2bfloat16(v.y);
    __nv_bfloat16 h2 = __float2bfloat16(v.z), h3 = __float2bfloat16(v.w);
    uint2 hv, lv;
    hv.x = pack_bf16(__bfloat162float(h0), __bfloat162float(h1));
    hv.y = pack_bf16(__bfloat162float(h2), __bfloat162float(h3));
    lv.x = pack_bf16(v.x - __bfloat162float(h0), v.y - __bfloat162float(h1));
    lv.y = pack_bf16(v.z - __bfloat162float(h2), v.w - __bfloat162float(h3));
    ((uint2*)g_hHi)[j] = hv;
    ((uint2*)g_hLo)[j] = lv;
}

// ---------------- 0c: transpose+split W (tiny) ----------------
__global__ void conv_w_kernel(const float* __restrict__ W) {
    int i = blockIdx.x * blockDim.x + threadIdx.x;  // i = n*128 + k
    if (i >= 128 * 128) return;
    int n = i >> 7, k = i & 127;
    float v = W[(size_t)k * 128 + n];
    __nv_bfloat16 hb = __float2bfloat16(v);
    g_WtHi[i] = hb;
    g_WtLo[i] = __float2bfloat16(v - __bfloat162float(hb));
}

// ================= tensor-core GEMM via mma.sync (verified R4 mainloop) =================
// feat = h@W + el/er dots. D = Ahi*Bhi + Alo*Bhi + Ahi*Blo (fp32 accum).
// CTA = 128 rows x 128 cols, K=128 staged fully in smem (pure vector copies).
#define ASTR 272                 // bytes per padded bf16 row (136 halves)
#define SM_A_HI 0
#define SM_A_LO 34816
#define SM_B_HI 69632
#define SM_B_LO 104448
#define SM_ATTN_L 139264
#define SM_ATTN_R 139776
#define SM_TOTAL 140288

__device__ __forceinline__ void mma_bf16(float* d, uint32_t a0, uint32_t a1, uint32_t a2,
                                         uint32_t a3, uint32_t b0, uint32_t b1) {
    asm volatile(
        "mma.sync.aligned.m16n8k16.row.col.f32.bf16.bf16.f32 "
        "{%0,%1,%2,%3}, {%4,%5,%6,%7}, {%8,%9}, {%0,%1,%2,%3};"
        : "+f"(d[0]), "+f"(d[1]), "+f"(d[2]), "+f"(d[3])
        : "r"(a0), "r"(a1), "r"(a2), "r"(a3), "r"(b0), "r"(b1));
}

__global__ void __launch_bounds__(256) gemm_tc_kernel(const float* __restrict__ attn_l,
                                                      const float* __restrict__ attn_r) {
    extern __shared__ char smem[];
    int tid = threadIdx.x;
    int lane = tid & 31, wid = tid >> 5;
    int row0 = blockIdx.x * 128;

    // ---- stage attn ----
    if (tid < 128) {
        *(float*)(smem + SM_ATTN_L + tid * 4) = attn_l[tid];
        *(float*)(smem + SM_ATTN_R + tid * 4) = attn_r[tid];
    }
    // ---- stage A tiles: pure uint4 copies from pre-split global ----
    for (int job = tid; job < 128 * 16; job += 256) {
        int r = job >> 4, c = job & 15;   // c = 16B chunk (8 bf16)
        int grow = row0 + r;
        uint4 hv = make_uint4(0, 0, 0, 0), lv = make_uint4(0, 0, 0, 0);
        if (grow < NN) {
            hv = *(const uint4*)(g_hHi + (size_t)grow * 128 + c * 8);
            lv = *(const uint4*)(g_hLo + (size_t)grow * 128 + c * 8);
        }
        *(uint4*)(smem + SM_A_HI + r * ASTR + c * 16) = hv;
        *(uint4*)(smem + SM_A_LO + r * ASTR + c * 16) = lv;
    }
    // ---- stage B tiles: pure uint4 copies ----
    for (int job = tid; job < 128 * 16; job += 256) {
        int n = job >> 4, c = job & 15;
        *(uint4*)(smem + SM_B_HI + n * ASTR + c * 16) = *(const uint4*)(g_WtHi + n * 128 + c * 8);
        *(uint4*)(smem + SM_B_LO + n * ASTR + c * 16) = *(const uint4*)(g_WtLo + n * 128 + c * 8);
    }
    __syncthreads();

    // ---- MMA mainloop (verified in R4): warp owns rows [wid*16, wid*16+16) ----
    int g = lane >> 2, tg = lane & 3;
    const char* Arow_hi = smem + SM_A_HI + (uint32_t)(wid * 16 + g) * ASTR;
    const char* Arow_lo = smem + SM_A_LO + (uint32_t)(wid * 16 + g) * ASTR;
    float d[16][4];
#pragma unroll
    for (int nt = 0; nt < 16; nt++) { d[nt][0] = d[nt][1] = d[nt][2] = d[nt][3] = 0.f; }

#pragma unroll
    for (int ks = 0; ks < 8; ks++) {
        uint32_t kb = ks * 32 + tg * 4;
        uint32_t ah0 = *(const uint32_t*)(Arow_hi + kb);
        uint32_t ah1 = *(const uint32_t*)(Arow_hi + 8 * ASTR + kb);
        uint32_t ah2 = *(const uint32_t*)(Arow_hi + kb + 16);
        uint32_t ah3 = *(const uint32_t*)(Arow_hi + 8 * ASTR + kb + 16);
        uint32_t al0 = *(const uint32_t*)(Arow_lo + kb);
        uint32_t al1 = *(const uint32_t*)(Arow_lo + 8 * ASTR + kb);
        uint32_t al2 = *(const uint32_t*)(Arow_lo + kb + 16);
        uint32_t al3 = *(const uint32_t*)(Arow_lo + 8 * ASTR + kb + 16);
#pragma unroll
        for (int nt = 0; nt < 16; nt++) {
            uint32_t nb = (uint32_t)(nt * 8 + g) * ASTR + kb;
            uint32_t bh0 = *(const uint32_t*)(smem + SM_B_HI + nb);
            uint32_t bh1 = *(const uint32_t*)(smem + SM_B_HI + nb + 16);
            uint32_t bl0 = *(const uint32_t*)(smem + SM_B_LO + nb);
            uint32_t bl1 = *(const uint32_t*)(smem + SM_B_LO + nb + 16);
            mma_bf16(d[nt], ah0, ah1, ah2, ah3, bh0, bh1);
            mma_bf16(d[nt], al0, al1, al2, al3, bh0, bh1);
            mma_bf16(d[nt], ah0, ah1, ah2, ah3, bl0, bl1);
        }
    }

    // ---- el/er dots from registers (R4 epilogue, verified) ----
    int r0 = row0 + wid * 16 + g;
    int r1 = r0 + 8;
    float el0h0 = 0.f, el0h1 = 0.f, er0h0 = 0.f, er0h1 = 0.f;
    float el1h0 = 0.f, el1h1 = 0.f, er1h0 = 0.f, er1h1 = 0.f;
    const float* alp = (const float*)(smem + SM_ATTN_L);
    const float* arp = (const float*)(smem + SM_ATTN_R);
#pragma unroll
    for (int nt = 0; nt < 16; nt++) {
        int c = nt * 8 + tg * 2;
        float a0 = alp[c], a1 = alp[c + 1], b0 = arp[c], b1 = arp[c + 1];
        float p0 = d[nt][0] * a0 + d[nt][1] * a1;
        float q0 = d[nt][0] * b0 + d[nt][1] * b1;
        float p1 = d[nt][2] * a0 + d[nt][3] * a1;
        float q1 = d[nt][2] * b0 + d[nt][3] * b1;
        if (nt < 8) { el0h0 += p0; er0h0 += q0; el1h0 += p1; er1h0 += q1; }
        else        { el0h1 += p0; er0h1 += q0; el1h1 += p1; er1h1 += q1; }
    }
#pragma unroll
    for (int off = 1; off <= 2; off <<= 1) {
        el0h0 += __shfl_xor_sync(0xffffffffu, el0h0, off);
        el0h1 += __shfl_xor_sync(0xffffffffu, el0h1, off);
        er0h0 += __shfl_xor_sync(0xffffffffu, er0h0, off);
        er0h1 += __shfl_xor_sync(0xffffffffu, er0h1, off);
        el1h0 += __shfl_xor_sync(0xffffffffu, el1h0, off);
        el1h1 += __shfl_xor_sync(0xffffffffu, el1h1, off);
        er1h0 += __shfl_xor_sync(0xffffffffu, er1h0, off);
        er1h1 += __shfl_xor_sync(0xffffffffu, er1h1, off);
    }
    if (tg == 0) {
        if (r0 < NN) {
            g_el[2 * r0] = el0h0; g_el[2 * r0 + 1] = el0h1;
            g_er[2 * r0] = er0h0; g_er[2 * r0 + 1] = er0h1;
        }
        if (r1 < NN) {
            g_el[2 * r1] = el1h0; g_el[2 * r1 + 1] = el1h1;
            g_er[2 * r1] = er1h0; g_er[2 * r1 + 1] = er1h1;
        }
    }

    // ---- feat: stage fp16 tile in smem (reuse A region), then coalesced store ----
    __syncthreads();   // all mainloop smem reads done
    {
        int r0l = wid * 16 + g, r1l = r0l + 8;
#pragma unroll
        for (int nt = 0; nt < 16; nt++) {
            int c = nt * 8 + tg * 2;
            __half2 q0 = __floats2half2_rn(d[nt][0], d[nt][1]);
            __half2 q1 = __floats2half2_rn(d[nt][2], d[nt][3]);
            *(__half2*)(smem + SM_A_HI + r0l * ASTR + c * 2) = q0;
            *(__half2*)(smem + SM_A_HI + r1l * ASTR + c * 2) = q1;
        }
    }
    __syncthreads();
    {
        int row = tid >> 1, half = tid & 1;
        int grow = row0 + row;
        if (grow < NN) {
            const uint4* s = (const uint4*)(smem + SM_A_HI + row * ASTR + half * 128);
            uint4* dg = (uint4*)(g_feat16 + (size_t)grow * 128 + half * 64);
#pragma unroll
            for (int q = 0; q < 8; q++) dg[q] = s[q];
        }
    }
}

// ---------------- 2: degree histogram ----------------
__global__ void hist_kernel(const int* __restrict__ dst) {
    int e = blockIdx.x * blockDim.x + threadIdx.x;
    if (e < EE) atomicAdd(&g_deg[dst[e]], 1);
}

// ---------------- 3a: per-chunk sums (chunk = 1024) ----------------
__global__ void chunk_sum_kernel() {
    int b = blockIdx.x, t = threadIdx.x;
    int base = b * 1024;
    int s = 0;
    for (int j = t; j < 1024; j += 256) {
        int i = base + j;
        s += (i < NN) ? g_deg[i] : 0;
    }
    __shared__ int sh[8];
#pragma unroll
    for (int off = 16; off; off >>= 1) s += __shfl_xor_sync(0xffffffffu, s, off);
    if ((t & 31) == 0) sh[t >> 5] = s;
    __syncthreads();
    if (t < 32) {
        int v = (t < 8) ? sh[t] : 0;
#pragma unroll
        for (int off = 4; off; off >>= 1) v += __shfl_xor_sync(0xffffffffu, v, off);
        if (t == 0) g_chunk_sum[b] = v;
    }
}

// ---------------- 3b: scan chunk sums (1 block) ----------------
__global__ void scan_chunks_kernel() {
    __shared__ int sh[128];
    int t = threadIdx.x;
    int v = (t < NCHUNK) ? g_chunk_sum[t] : 0;
    sh[t] = v;
    __syncthreads();
    for (int off = 1; off < 128; off <<= 1) {
        int a = (t >= off) ? sh[t - off] : 0;
        __syncthreads();
        sh[t] += a;
        __syncthreads();
    }
    if (t < NCHUNK) g_chunk_excl[t] = sh[t] - v;
}

// ---------------- 3c: finalize row_ptr / cursor ----------------
__global__ void scan_final_kernel() {
    int i = blockIdx.x * 1024 + threadIdx.x;
    int lane = threadIdx.x & 31, wid = threadIdx.x >> 5;
    int v = (i < NN) ? g_deg[i] : 0;
    int x = v;
#pragma unroll
    for (int off = 1; off < 32; off <<= 1) {
        int y = __shfl_up_sync(0xffffffffu, x, off);
        if (lane >= off) x += y;
    }
    __shared__ int sh[32];
    if (lane == 31) sh[wid] = x;
    __syncthreads();
    if (wid == 0) {
        int y = sh[lane];
#pragma unroll
        for (int off = 1; off < 32; off <<= 1) {
            int z = __shfl_up_sync(0xffffffffu, y, off);
            if (lane >= off) y += z;
        }
        sh[lane] = y;
    }
    __syncthreads();
    int incl = x + (wid ? sh[wid - 1] : 0);
    int base = g_chunk_excl[blockIdx.x];
    if (i < NN) {
        int excl = base + incl - v;
        g_rowptr[i] = excl;
        g_cursor[i] = excl;
    }
    if (i == NN - 1) g_rowptr[NN] = base + incl;
}

// ---------------- 4: scatter edges into CSR order with exp(logit), 8B entries ----------------
__global__ void scatter_kernel(const int* __restrict__ src, const int* __restrict__ dst) {
    int e = blockIdx.x * blockDim.x + threadIdx.x;
    if (e >= EE) return;
    int s = src[e], d = dst[e];
    int p = atomicAdd(&g_cursor[d], 1);
    float e0 = g_el[2 * s]     + g_er[2 * d];
    float e1 = g_el[2 * s + 1] + g_er[2 * d + 1];
    e0 = (e0 > 0.f) ? e0 : NEG_SLOPE * e0;
    e1 = (e1 > 0.f) ? e1 : NEG_SLOPE * e1;
    __half2 w = __floats2half2_rn(__expf(e0), __expf(e1));
    g_csr[p] = make_uint2((uint32_t)s, *(uint32_t*)&w);
}

// ---------------- 5: per-node weighted aggregate + fused LayerNorm ----------------
__global__ void agg_ln_kernel(const float* __restrict__ bias, const float* __restrict__ gamma,
                              const float* __restrict__ beta, float* __restrict__ out) {
    int gwarp = (blockIdx.x * blockDim.x + threadIdx.x) >> 5;
    int lane = threadIdx.x & 31;
    if (gwarp >= NN) return;
    int beg = g_rowptr[gwarp], end = g_rowptr[gwarp + 1];
    bool h1 = (lane >= 16);

    float4 acc = make_float4(0.f, 0.f, 0.f, 0.f);
    float wsum = 0.f;
    int i = beg;
    for (; i + 2 <= end; i += 2) {
        uint2 c0 = g_csr[i], c1 = g_csr[i + 1];
        uint2 u0 = ((const uint2*)(g_feat16 + (size_t)c0.x * 128))[lane];
        uint2 u1 = ((const uint2*)(g_feat16 + (size_t)c1.x * 128))[lane];
        __half2 wh0 = *(__half2*)&c0.y, wh1 = *(__half2*)&c1.y;
        float w0 = h1 ? __high2float(wh0) : __low2float(wh0);
        float w1 = h1 ? __high2float(wh1) : __low2float(wh1);
        float2 v0a = __half22float2(*(__half2*)&u0.x);
        float2 v0b = __half22float2(*(__half2*)&u0.y);
        float2 v1a = __half22float2(*(__half2*)&u1.x);
        float2 v1b = __half22float2(*(__half2*)&u1.y);
        wsum += w0 + w1;
        acc.x += w0 * v0a.x + w1 * v1a.x;
        acc.y += w0 * v0a.y + w1 * v1a.y;
        acc.z += w0 * v0b.x + w1 * v1b.x;
        acc.w += w0 * v0b.y + w1 * v1b.y;
    }
    if (i < end) {
        uint2 c0 = g_csr[i];
        uint2 u0 = ((const uint2*)(g_feat16 + (size_t)c0.x * 128))[lane];
        __half2 wh0 = *(__half2*)&c0.y;
        float w0 = h1 ? __high2float(wh0) : __low2float(wh0);
        float2 v0a = __half22float2(*(__half2*)&u0.x);
        float2 v0b = __half22float2(*(__half2*)&u0.y);
        wsum += w0;
        acc.x += w0 * v0a.x; acc.y += w0 * v0a.y;
        acc.z += w0 * v0b.x; acc.w += w0 * v0b.y;
    }
    float inv = (end > beg) ? 1.0f / wsum : 0.f;

    float4 b4 = ((const float4*)bias)[lane];
    float4 x;
    x.x = acc.x * inv + b4.x; x.y = acc.y * inv + b4.y;
    x.z = acc.z * inv + b4.z; x.w = acc.w * inv + b4.w;

    float s = x.x + x.y + x.z + x.w;
#pragma unroll
    for (int off = 16; off; off >>= 1) s += __shfl_xor_sync(0xffffffffu, s, off);
    float mu = s * (1.f / 128.f);
    float dx0 = x.x - mu, dx1 = x.y - mu, dx2 = x.z - mu, dx3 = x.w - mu;
    float ss = dx0 * dx0 + dx1 * dx1 + dx2 * dx2 + dx3 * dx3;
#pragma unroll
    for (int off = 16; off; off >>= 1) ss += __shfl_xor_sync(0xffffffffu, ss, off);
    float istd = rsqrtf(ss * (1.f / 128.f) + LN_EPS);

    float4 g4 = ((const float4*)gamma)[lane];
    float4 be4 = ((const float4*)beta)[lane];
    float4 y;
    y.x = g4.x * dx0 * istd + be4.x;
    y.y = g4.y * dx1 * istd + be4.y;
    y.z = g4.z * dx2 * istd + be4.z;
    y.w = g4.w * dx3 * istd + be4.w;
    ((float4*)(out + (size_t)gwarp * 128))[lane] = y;
}

// ---------------- launch ----------------
extern "C" void kernel_launch(void* const* d_in, const int* in_sizes, int n_in,
                              void* d_out, int out_size) {
    const float* h      = (const float*)d_in[0];
    const int*   src    = (const int*)d_in[1];
    const int*   dst    = (const int*)d_in[2];
    const float* W      = (const float*)d_in[3];
    const float* attn_l = (const float*)d_in[4];
    const float* attn_r = (const float*)d_in[5];
    const float* bias   = (const float*)d_in[6];
    const float* gamma  = (const float*)d_in[7];
    const float* beta   = (const float*)d_in[8];
    float* out = (float*)d_out;

    static cudaStream_t s1 = nullptr;
    static cudaEvent_t evRoot = nullptr, evSide = nullptr;
    if (!s1) {
        cudaStreamCreateWithFlags(&s1, cudaStreamNonBlocking);
        cudaEventCreateWithFlags(&evRoot, cudaEventDisableTiming);
        cudaEventCreateWithFlags(&evSide, cudaEventDisableTiming);
    }
    cudaFuncSetAttribute(gemm_tc_kernel, cudaFuncAttributeMaxDynamicSharedMemorySize, SM_TOTAL);

    // fork: CSR-build chain on s1 (independent of gemm path)
    cudaEventRecord(evRoot, 0);
    cudaStreamWaitEvent(s1, evRoot, 0);
    zero_deg_kernel<<<(NN + 255) / 256, 256, 0, s1>>>();
    hist_kernel<<<(EE + 255) / 256, 256, 0, s1>>>(dst);
    chunk_sum_kernel<<<NCHUNK, 256, 0, s1>>>();
    scan_chunks_kernel<<<1, 128, 0, s1>>>();
    scan_final_kernel<<<NCHUNK, 1024, 0, s1>>>();
    cudaEventRecord(evSide, s1);

    // main: split-precision prep, tensor-core gemm
    conv_h_kernel<<<(NN * 32 + 255) / 256, 256>>>(h);
    conv_w_kernel<<<64, 256>>>(W);
    gemm_tc_kernel<<<(NN + 127) / 128, 256, SM_TOTAL>>>(attn_l, attn_r);

    // join: scatter needs el/er (main) + cursor (side)
    cudaStreamWaitEvent(0, evSide, 0);
    scatter_kernel<<<(EE + 255) / 256, 256>>>(src, dst);
    agg_ln_kernel<<<(NN * 32 + 255) / 256, 256>>>(bias, gamma, beta, out);
}

// round 10
// speedup vs baseline: 1.1755x; 1.0231x over previous
#include <cuda_runtime.h>
#include <cuda_fp16.h>
#include <cuda_bf16.h>
#include <cstdint>

#define NN 100000
#define EE 1600000
#define NEG_SLOPE 0.2f
#define LN_EPS 1e-5f
#define NCHUNK 98  // ceil(NN/1024)

// ---------------- scratch (device globals; no allocation allowed) ----------------
__device__ __half         g_feat16[(size_t)NN * 128]; // h @ W in fp16 (25.6 MB)
__device__ __nv_bfloat16  g_hHi[(size_t)NN * 128];    // bf16 hi split of h (25.6 MB)
__device__ __nv_bfloat16  g_hLo[(size_t)NN * 128];    // bf16 lo split of h (25.6 MB)
__device__ __nv_bfloat16  g_WtHi[128 * 128];          // Wt[n][k] hi
__device__ __nv_bfloat16  g_WtLo[128 * 128];          // Wt[n][k] lo
__device__ float   g_el[NN * 2];
__device__ float   g_er[NN * 2];
__device__ int     g_deg[NN];
__device__ int     g_rowptr[NN + 1];
__device__ int     g_cursor[NN];
__device__ int     g_chunk_sum[128];
__device__ int     g_chunk_excl[128];
__device__ int     g_srcIdx[EE];               // CSR: src index per edge (4B/edge)

__device__ __forceinline__ uint32_t pack_bf16(float a, float b) {
    __nv_bfloat162 t = __floats2bfloat162_rn(a, b);
    return *reinterpret_cast<uint32_t*>(&t);
}

// ---------------- 0: zero degree counters ----------------
__global__ void zero_deg_kernel() {
    int i = blockIdx.x * blockDim.x + threadIdx.x;
    if (i < NN) g_deg[i] = 0;
}

// ---------------- 0b: split h into bf16 hi/lo (streaming) ----------------
__global__ void conv_h_kernel(const float* __restrict__ h) {
    size_t j = (size_t)blockIdx.x * blockDim.x + threadIdx.x;  // one float4
    if (j >= (size_t)NN * 32) return;
    float4 v = ((const float4*)h)[j];
    __nv_bfloat16 h0 = __float2bfloat16(v.x), h1 = __float2bfloat16(v.y);
    __nv_bfloat16 h2 = __float2bfloat16(v.z), h3 = __float2bfloat16(v.w);
    uint2 hv, lv;
    hv.x = pack_bf16(__bfloat162float(h0), __bfloat162float(h1));
    hv.y = pack_bf16(__bfloat162float(h2), __bfloat162float(h3));
    lv.x = pack_bf16(v.x - __bfloat162float(h0), v.y - __bfloat162float(h1));
    lv.y = pack_bf16(v.z - __bfloat162float(h2), v.w - __bfloat162float(h3));
    ((uint2*)g_hHi)[j] = hv;
    ((uint2*)g_hLo)[j] = lv;
}

// ---------------- 0c: transpose+split W (tiny) ----------------
__global__ void conv_w_kernel(const float* __restrict__ W) {
    int i = blockIdx.x * blockDim.x + threadIdx.x;  // i = n*128 + k
    if (i >= 128 * 128) return;
    int n = i >> 7, k = i & 127;
    float v = W[(size_t)k * 128 + n];
    __nv_bfloat16 hb = __float2bfloat16(v);
    g_WtHi[i] = hb;
    g_WtLo[i] = __float2bfloat16(v - __bfloat162float(hb));
}

// ================= tensor-core GEMM via mma.sync (verified mainloop) =================
#define ASTR 272                 // bytes per padded bf16 row (136 halves)
#define SM_A_HI 0
#define SM_A_LO 34816
#define SM_B_HI 69632
#define SM_B_LO 104448
#define SM_ATTN_L 139264
#define SM_ATTN_R 139776
#define SM_TOTAL 140288

__device__ __forceinline__ void mma_bf16(float* d, uint32_t a0, uint32_t a1, uint32_t a2,
                                         uint32_t a3, uint32_t b0, uint32_t b1) {
    asm volatile(
        "mma.sync.aligned.m16n8k16.row.col.f32.bf16.bf16.f32 "
        "{%0,%1,%2,%3}, {%4,%5,%6,%7}, {%8,%9}, {%0,%1,%2,%3};"
        : "+f"(d[0]), "+f"(d[1]), "+f"(d[2]), "+f"(d[3])
        : "r"(a0), "r"(a1), "r"(a2), "r"(a3), "r"(b0), "r"(b1));
}

__global__ void __launch_bounds__(256) gemm_tc_kernel(const float* __restrict__ attn_l,
                                                      const float* __restrict__ attn_r) {
    extern __shared__ char smem[];
    int tid = threadIdx.x;
    int lane = tid & 31, wid = tid >> 5;
    int row0 = blockIdx.x * 128;

    if (tid < 128) {
        *(float*)(smem + SM_ATTN_L + tid * 4) = attn_l[tid];
        *(float*)(smem + SM_ATTN_R + tid * 4) = attn_r[tid];
    }
    for (int job = tid; job < 128 * 16; job += 256) {
        int r = job >> 4, c = job & 15;
        int grow = row0 + r;
        uint4 hv = make_uint4(0, 0, 0, 0), lv = make_uint4(0, 0, 0, 0);
        if (grow < NN) {
            hv = *(const uint4*)(g_hHi + (size_t)grow * 128 + c * 8);
            lv = *(const uint4*)(g_hLo + (size_t)grow * 128 + c * 8);
        }
        *(uint4*)(smem + SM_A_HI + r * ASTR + c * 16) = hv;
        *(uint4*)(smem + SM_A_LO + r * ASTR + c * 16) = lv;
    }
    for (int job = tid; job < 128 * 16; job += 256) {
        int n = job >> 4, c = job & 15;
        *(uint4*)(smem + SM_B_HI + n * ASTR + c * 16) = *(const uint4*)(g_WtHi + n * 128 + c * 8);
        *(uint4*)(smem + SM_B_LO + n * ASTR + c * 16) = *(const uint4*)(g_WtLo + n * 128 + c * 8);
    }
    __syncthreads();

    int g = lane >> 2, tg = lane & 3;
    const char* Arow_hi = smem + SM_A_HI + (uint32_t)(wid * 16 + g) * ASTR;
    const char* Arow_lo = smem + SM_A_LO + (uint32_t)(wid * 16 + g) * ASTR;
    float d[16][4];
#pragma unroll
    for (int nt = 0; nt < 16; nt++) { d[nt][0] = d[nt][1] = d[nt][2] = d[nt][3] = 0.f; }

#pragma unroll
    for (int ks = 0; ks < 8; ks++) {
        uint32_t kb = ks * 32 + tg * 4;
        uint32_t ah0 = *(const uint32_t*)(Arow_hi + kb);
        uint32_t ah1 = *(const uint32_t*)(Arow_hi + 8 * ASTR + kb);
        uint32_t ah2 = *(const uint32_t*)(Arow_hi + kb + 16);
        uint32_t ah3 = *(const uint32_t*)(Arow_hi + 8 * ASTR + kb + 16);
        uint32_t al0 = *(const uint32_t*)(Arow_lo + kb);
        uint32_t al1 = *(const uint32_t*)(Arow_lo + 8 * ASTR + kb);
        uint32_t al2 = *(const uint32_t*)(Arow_lo + kb + 16);
        uint32_t al3 = *(const uint32_t*)(Arow_lo + 8 * ASTR + kb + 16);
#pragma unroll
        for (int nt = 0; nt < 16; nt++) {
            uint32_t nb = (uint32_t)(nt * 8 + g) * ASTR + kb;
            uint32_t bh0 = *(const uint32_t*)(smem + SM_B_HI + nb);
            uint32_t bh1 = *(const uint32_t*)(smem + SM_B_HI + nb + 16);
            uint32_t bl0 = *(const uint32_t*)(smem + SM_B_LO + nb);
            uint32_t bl1 = *(const uint32_t*)(smem + SM_B_LO + nb + 16);
            mma_bf16(d[nt], ah0, ah1, ah2, ah3, bh0, bh1);
            mma_bf16(d[nt], al0, al1, al2, al3, bh0, bh1);
            mma_bf16(d[nt], ah0, ah1, ah2, ah3, bl0, bl1);
        }
    }

    // ---- el/er dots from registers ----
    int r0 = row0 + wid * 16 + g;
    int r1 = r0 + 8;
    float el0h0 = 0.f, el0h1 = 0.f, er0h0 = 0.f, er0h1 = 0.f;
    float el1h0 = 0.f, el1h1 = 0.f, er1h0 = 0.f, er1h1 = 0.f;
    const float* alp = (const float*)(smem + SM_ATTN_L);
    const float* arp = (const float*)(smem + SM_ATTN_R);
#pragma unroll
    for (int nt = 0; nt < 16; nt++) {
        int c = nt * 8 + tg * 2;
        float a0 = alp[c], a1 = alp[c + 1], b0 = arp[c], b1 = arp[c + 1];
        float p0 = d[nt][0] * a0 + d[nt][1] * a1;
        float q0 = d[nt][0] * b0 + d[nt][1] * b1;
        float p1 = d[nt][2] * a0 + d[nt][3] * a1;
        float q1 = d[nt][2] * b0 + d[nt][3] * b1;
        if (nt < 8) { el0h0 += p0; er0h0 += q0; el1h0 += p1; er1h0 += q1; }
        else        { el0h1 += p0; er0h1 += q0; el1h1 += p1; er1h1 += q1; }
    }
#pragma unroll
    for (int off = 1; off <= 2; off <<= 1) {
        el0h0 += __shfl_xor_sync(0xffffffffu, el0h0, off);
        el0h1 += __shfl_xor_sync(0xffffffffu, el0h1, off);
        er0h0 += __shfl_xor_sync(0xffffffffu, er0h0, off);
        er0h1 += __shfl_xor_sync(0xffffffffu, er0h1, off);
        el1h0 += __shfl_xor_sync(0xffffffffu, el1h0, off);
        el1h1 += __shfl_xor_sync(0xffffffffu, el1h1, off);
        er1h0 += __shfl_xor_sync(0xffffffffu, er1h0, off);
        er1h1 += __shfl_xor_sync(0xffffffffu, er1h1, off);
    }
    if (tg == 0) {
        if (r0 < NN) {
            g_el[2 * r0] = el0h0; g_el[2 * r0 + 1] = el0h1;
            g_er[2 * r0] = er0h0; g_er[2 * r0 + 1] = er0h1;
        }
        if (r1 < NN) {
            g_el[2 * r1] = el1h0; g_el[2 * r1 + 1] = el1h1;
            g_er[2 * r1] = er1h0; g_er[2 * r1 + 1] = er1h1;
        }
    }

    // ---- feat: stage fp16 tile in smem (reuse A region), then coalesced store ----
    __syncthreads();
    {
        int r0l = wid * 16 + g, r1l = r0l + 8;
#pragma unroll
        for (int nt = 0; nt < 16; nt++) {
            int c = nt * 8 + tg * 2;
            __half2 q0 = __floats2half2_rn(d[nt][0], d[nt][1]);
            __half2 q1 = __floats2half2_rn(d[nt][2], d[nt][3]);
            *(__half2*)(smem + SM_A_HI + r0l * ASTR + c * 2) = q0;
            *(__half2*)(smem + SM_A_HI + r1l * ASTR + c * 2) = q1;
        }
    }
    __syncthreads();
    {
        int row = tid >> 1, half = tid & 1;
        int grow = row0 + row;
        if (grow < NN) {
            const uint4* s = (const uint4*)(smem + SM_A_HI + row * ASTR + half * 128);
            uint4* dg = (uint4*)(g_feat16 + (size_t)grow * 128 + half * 64);
#pragma unroll
            for (int q = 0; q < 8; q++) dg[q] = s[q];
        }
    }
}

// ---------------- 2: degree histogram ----------------
__global__ void hist_kernel(const int* __restrict__ dst) {
    int e = blockIdx.x * blockDim.x + threadIdx.x;
    if (e < EE) atomicAdd(&g_deg[dst[e]], 1);
}

// ---------------- 3a: per-chunk sums (chunk = 1024) ----------------
__global__ void chunk_sum_kernel() {
    int b = blockIdx.x, t = threadIdx.x;
    int base = b * 1024;
    int s = 0;
    for (int j = t; j < 1024; j += 256) {
        int i = base + j;
        s += (i < NN) ? g_deg[i] : 0;
    }
    __shared__ int sh[8];
#pragma unroll
    for (int off = 16; off; off >>= 1) s += __shfl_xor_sync(0xffffffffu, s, off);
    if ((t & 31) == 0) sh[t >> 5] = s;
    __syncthreads();
    if (t < 32) {
        int v = (t < 8) ? sh[t] : 0;
#pragma unroll
        for (int off = 4; off; off >>= 1) v += __shfl_xor_sync(0xffffffffu, v, off);
        if (t == 0) g_chunk_sum[b] = v;
    }
}

// ---------------- 3b: scan chunk sums (1 block) ----------------
__global__ void scan_chunks_kernel() {
    __shared__ int sh[128];
    int t = threadIdx.x;
    int v = (t < NCHUNK) ? g_chunk_sum[t] : 0;
    sh[t] = v;
    __syncthreads();
    for (int off = 1; off < 128; off <<= 1) {
        int a = (t >= off) ? sh[t - off] : 0;
        __syncthreads();
        sh[t] += a;
        __syncthreads();
    }
    if (t < NCHUNK) g_chunk_excl[t] = sh[t] - v;
}

// ---------------- 3c: finalize row_ptr / cursor ----------------
__global__ void scan_final_kernel() {
    int i = blockIdx.x * 1024 + threadIdx.x;
    int lane = threadIdx.x & 31, wid = threadIdx.x >> 5;
    int v = (i < NN) ? g_deg[i] : 0;
    int x = v;
#pragma unroll
    for (int off = 1; off < 32; off <<= 1) {
        int y = __shfl_up_sync(0xffffffffu, x, off);
        if (lane >= off) x += y;
    }
    __shared__ int sh[32];
    if (lane == 31) sh[wid] = x;
    __syncthreads();
    if (wid == 0) {
        int y = sh[lane];
#pragma unroll
        for (int off = 1; off < 32; off <<= 1) {
            int z = __shfl_up_sync(0xffffffffu, y, off);
            if (lane >= off) y += z;
        }
        sh[lane] = y;
    }
    __syncthreads();
    int incl = x + (wid ? sh[wid - 1] : 0);
    int base = g_chunk_excl[blockIdx.x];
    if (i < NN) {
        int excl = base + incl - v;
        g_rowptr[i] = excl;
        g_cursor[i] = excl;
    }
    if (i == NN - 1) g_rowptr[NN] = base + incl;
}

// ---------------- 4: scatter src indices into CSR order (logit-free!) ----------------
__global__ void scatter_idx_kernel(const int* __restrict__ src, const int* __restrict__ dst) {
    int e = blockIdx.x * blockDim.x + threadIdx.x;
    if (e >= EE) return;
    int d = dst[e];
    int p = atomicAdd(&g_cursor[d], 1);
    g_srcIdx[p] = src[e];
}

// ---------------- 5: per-node softmax-aggregate + fused LayerNorm ----------------
// One warp per node. Lanes 0-15 = head0 cols, 16-31 = head1.
// Edge weight computed in-kernel: w = exp(leaky(el[src,h] + er[node,h])).
__global__ void agg_ln_kernel(const float* __restrict__ bias, const float* __restrict__ gamma,
                              const float* __restrict__ beta, float* __restrict__ out) {
    int gwarp = (blockIdx.x * blockDim.x + threadIdx.x) >> 5;
    int lane = threadIdx.x & 31;
    if (gwarp >= NN) return;
    int beg = g_rowptr[gwarp], end = g_rowptr[gwarp + 1];
    int hh = (lane >= 16) ? 1 : 0;
    float er_d = g_er[2 * gwarp + hh];

    float4 acc = make_float4(0.f, 0.f, 0.f, 0.f);
    float wsum = 0.f;
    int i = beg;
    for (; i + 2 <= end; i += 2) {
        int s0 = g_srcIdx[i], s1 = g_srcIdx[i + 1];
        uint2 u0 = ((const uint2*)(g_feat16 + (size_t)s0 * 128))[lane];
        uint2 u1 = ((const uint2*)(g_feat16 + (size_t)s1 * 128))[lane];
        float e0 = g_el[2 * s0 + hh] + er_d;
        float e1 = g_el[2 * s1 + hh] + er_d;
        e0 = (e0 > 0.f) ? e0 : NEG_SLOPE * e0;
        e1 = (e1 > 0.f) ? e1 : NEG_SLOPE * e1;
        float w0 = __expf(e0), w1 = __expf(e1);
        float2 v0a = __half22float2(*(__half2*)&u0.x);
        float2 v0b = __half22float2(*(__half2*)&u0.y);
        float2 v1a = __half22float2(*(__half2*)&u1.x);
        float2 v1b = __half22float2(*(__half2*)&u1.y);
        wsum += w0 + w1;
        acc.x += w0 * v0a.x + w1 * v1a.x;
        acc.y += w0 * v0a.y + w1 * v1a.y;
        acc.z += w0 * v0b.x + w1 * v1b.x;
        acc.w += w0 * v0b.y + w1 * v1b.y;
    }
    if (i < end) {
        int s0 = g_srcIdx[i];
        uint2 u0 = ((const uint2*)(g_feat16 + (size_t)s0 * 128))[lane];
        float e0 = g_el[2 * s0 + hh] + er_d;
        e0 = (e0 > 0.f) ? e0 : NEG_SLOPE * e0;
        float w0 = __expf(e0);
        float2 v0a = __half22float2(*(__half2*)&u0.x);
        float2 v0b = __half22float2(*(__half2*)&u0.y);
        wsum += w0;
        acc.x += w0 * v0a.x; acc.y += w0 * v0a.y;
        acc.z += w0 * v0b.x; acc.w += w0 * v0b.y;
    }
    float inv = (end > beg) ? 1.0f / wsum : 0.f;

    float4 b4 = ((const float4*)bias)[lane];
    float4 x;
    x.x = acc.x * inv + b4.x; x.y = acc.y * inv + b4.y;
    x.z = acc.z * inv + b4.z; x.w = acc.w * inv + b4.w;

    float s = x.x + x.y + x.z + x.w;
#pragma unroll
    for (int off = 16; off; off >>= 1) s += __shfl_xor_sync(0xffffffffu, s, off);
    float mu = s * (1.f / 128.f);
    float dx0 = x.x - mu, dx1 = x.y - mu, dx2 = x.z - mu, dx3 = x.w - mu;
    float ss = dx0 * dx0 + dx1 * dx1 + dx2 * dx2 + dx3 * dx3;
#pragma unroll
    for (int off = 16; off; off >>= 1) ss += __shfl_xor_sync(0xffffffffu, ss, off);
    float istd = rsqrtf(ss * (1.f / 128.f) + LN_EPS);

    float4 g4 = ((const float4*)gamma)[lane];
    float4 be4 = ((const float4*)beta)[lane];
    float4 y;
    y.x = g4.x * dx0 * istd + be4.x;
    y.y = g4.y * dx1 * istd + be4.y;
    y.z = g4.z * dx2 * istd + be4.z;
    y.w = g4.w * dx3 * istd + be4.w;
    ((float4*)(out + (size_t)gwarp * 128))[lane] = y;
}

// ---------------- launch ----------------
extern "C" void kernel_launch(void* const* d_in, const int* in_sizes, int n_in,
                              void* d_out, int out_size) {
    const float* h      = (const float*)d_in[0];
    const int*   src    = (const int*)d_in[1];
    const int*   dst    = (const int*)d_in[2];
    const float* W      = (const float*)d_in[3];
    const float* attn_l = (const float*)d_in[4];
    const float* attn_r = (const float*)d_in[5];
    const float* bias   = (const float*)d_in[6];
    const float* gamma  = (const float*)d_in[7];
    const float* beta   = (const float*)d_in[8];
    float* out = (float*)d_out;

    static cudaStream_t s1 = nullptr;
    static cudaEvent_t evRoot = nullptr, evSide = nullptr;
    if (!s1) {
        cudaStreamCreateWithFlags(&s1, cudaStreamNonBlocking);
        cudaEventCreateWithFlags(&evRoot, cudaEventDisableTiming);
        cudaEventCreateWithFlags(&evSide, cudaEventDisableTiming);
    }
    cudaFuncSetAttribute(gemm_tc_kernel, cudaFuncAttributeMaxDynamicSharedMemorySize, SM_TOTAL);

    // fork: FULL CSR chain incl. index scatter on s1 (logit-free; independent of gemm)
    cudaEventRecord(evRoot, 0);
    cudaStreamWaitEvent(s1, evRoot, 0);
    zero_deg_kernel<<<(NN + 255) / 256, 256, 0, s1>>>();
    hist_kernel<<<(EE + 255) / 256, 256, 0, s1>>>(dst);
    chunk_sum_kernel<<<NCHUNK, 256, 0, s1>>>();
    scan_chunks_kernel<<<1, 128, 0, s1>>>();
    scan_final_kernel<<<NCHUNK, 1024, 0, s1>>>();
    scatter_idx_kernel<<<(EE + 255) / 256, 256, 0, s1>>>(src, dst);
    cudaEventRecord(evSide, s1);

    // main: split-precision prep, tensor-core gemm (feat + el/er)
    conv_h_kernel<<<(NN * 32 + 255) / 256, 256>>>(h);
    conv_w_kernel<<<64, 256>>>(W);
    gemm_tc_kernel<<<(NN + 127) / 128, 256, SM_TOTAL>>>(attn_l, attn_r);

    // join: agg needs feat+el/er (main) + srcIdx (side)
    cudaStreamWaitEvent(0, evSide, 0);
    agg_ln_kernel<<<(NN * 32 + 255) / 256, 256>>>(bias, gamma, beta, out);
}